// round 7
// baseline (speedup 1.0000x reference)
#include <cuda_runtime.h>
#include <math.h>

#define NN   100000
#define EE   500000
#define SLOPE 0.01f
typedef unsigned long long ull;

// ---------------- scratch ----------------
__device__ float g_FS [2 * NN * 96];
__device__ float g_RES[2 * NN * 96];
__device__ float g_EL [2 * NN * 3];
__device__ float g_ER [2 * NN * 3];
__device__ float g_GU [NN * 96];
__device__ float g_GI [NN * 96];
__device__ float g_HU [NN * 32];
__device__ float g_HI [NN * 32];
__device__ float g_WR [4 * 64 * 3];
// joint CSR
__device__ int g_deg [2 * NN];      // zeroed at end of every call (and statically)
__device__ int g_off [2 * NN];
__device__ int g_cur [2 * NN];
__device__ int g_eidx[2 * EE];
// lookback scan state (zeroed at end of every call)
__device__ unsigned g_state[256];
__device__ int g_ticket;

// ---------------- f32x2 helpers ----------------
__device__ __forceinline__ ull pack2(float x, float y) {
    ull r; asm("mov.b64 %0, {%1, %2};" : "=l"(r) : "f"(x), "f"(y)); return r;
}
__device__ __forceinline__ void ffma2(ull& d, ull a, ull b) {
    asm("fma.rn.f32x2 %0, %1, %2, %0;" : "+l"(d) : "l"(a), "l"(b));
}
__device__ __forceinline__ void unpack2(float& x, float& y, ull v) {
    asm("mov.b64 {%0, %1}, %2;" : "=f"(x), "=f"(y) : "l"(v));
}

// ---------------- WR helper (device-side section) ----------------
__device__ void wr_section(const float* W0, const float* W1, const float* attn,
                           float* WR, int K, int i) {
    if (i >= 4 * K * 3) return;
    int c = i / (K * 3);
    int rem = i - c * K * 3;
    int k = rem / 3, h = rem - k * 3;
    const float* W = (c < 2) ? W0 : W1;
    const float* a = attn + c * 96 + h * 32;
    const float* wrow = W + k * 96 + h * 32;
    float s = 0.f;
    #pragma unroll
    for (int d = 0; d < 32; d++) s += wrow[d] * a[d];
    WR[i] = s;
}

// ---------------- launch 1: count (both relations) + WR layer1 ----------------
__global__ void pre_kernel(const int* __restrict__ d0, const int* __restrict__ d1,
                           int* __restrict__ deg,
                           const float* __restrict__ W0, const float* __restrict__ W1,
                           const float* __restrict__ attn, float* __restrict__ WR,
                           int K, int ne) {
    int t = threadIdx.x;
    int i = blockIdx.x * 256 + t;
    if (blockIdx.y == 0) {
        if (i < ne) atomicAdd(&deg[d0[i]], 1);
    } else if (blockIdx.y == 1) {
        if (i < ne) atomicAdd(&deg[NN + d1[i]], 1);
    } else {
        wr_section(W0, W1, attn, WR, K, i);
    }
}

// ---------------- launch 2: single-pass decoupled-lookback exclusive scan ----------------
// in: deg[0..n), out: off, cur.  state/ticket pre-zeroed.
__global__ void scan_lb_kernel(const int* __restrict__ in, int* __restrict__ off,
                               int* __restrict__ cur, int n) {
    __shared__ int sh[1024];
    __shared__ int s_tile;
    __shared__ int s_prefix;
    const int t = threadIdx.x;
    if (t == 0) s_tile = atomicAdd(&g_ticket, 1);
    __syncthreads();
    const int tile = s_tile;
    const int i = tile * 1024 + t;
    int v = (i < n) ? in[i] : 0;
    sh[t] = v; __syncthreads();
    for (int ofs = 1; ofs < 1024; ofs <<= 1) {
        int tv = (t >= ofs) ? sh[t - ofs] : 0;
        __syncthreads();
        sh[t] += tv;
        __syncthreads();
    }
    const int inc = sh[t];          // inclusive within tile
    const int total = sh[1023];

    if (t == 0) {
        if (tile == 0) {
            atomicExch(&g_state[0], (2u << 30) | (unsigned)total);
            s_prefix = 0;
        } else {
            atomicExch(&g_state[tile], (1u << 30) | (unsigned)total);
            int prefix = 0;
            int tt = tile - 1;
            while (true) {
                unsigned st = *(volatile unsigned*)&g_state[tt];
                unsigned tag = st >> 30;
                if (tag == 2u) { prefix += (int)(st & 0x3FFFFFFFu); break; }
                if (tag == 1u) { prefix += (int)(st & 0x3FFFFFFFu); --tt; }
                // tag==0: spin
            }
            atomicExch(&g_state[tile], (2u << 30) | (unsigned)(prefix + total));
            s_prefix = prefix;
        }
    }
    __syncthreads();
    if (i < n) {
        int excl = s_prefix + inc - v;
        off[i] = excl;
        cur[i] = excl;
    }
}

// ---------------- launch 3/6: quad GEMM + attn tail (+ optional scatter sections) ----------------
// y<4: GEMM out[N,96]=X@W, tile 64 rows, f32x2; tail thread t<64 computes attn scores.
// y==4/5 (DO_SCATTER): CSR scatter for rel0/rel1.
template <int K, bool DO_SCATTER>
__global__ void mega_kernel(const float* __restrict__ Xa, const float* __restrict__ Wa,
                            float* __restrict__ Oa,
                            const float* __restrict__ Xb, const float* __restrict__ Wb,
                            float* __restrict__ Ob,
                            const float* __restrict__ Xc, const float* __restrict__ Wc,
                            float* __restrict__ Oc,
                            const float* __restrict__ Xd, const float* __restrict__ Wd,
                            float* __restrict__ Od,
                            const float* __restrict__ WR4,
                            float* __restrict__ S0, float* __restrict__ S1,
                            float* __restrict__ S2, float* __restrict__ S3,
                            const int* __restrict__ s0, const int* __restrict__ d0,
                            const int* __restrict__ s1, const int* __restrict__ d1,
                            int* __restrict__ cur, int* __restrict__ eidx,
                            int N, int ne, int gemmBlocks) {
    const int t = threadIdx.y * 24 + threadIdx.x;

    if (DO_SCATTER && blockIdx.y >= 4) {
        int e = blockIdx.x * 192 + t;
        if (e < ne) {
            int src, dj;
            if (blockIdx.y == 4) { src = s0[e]; dj = d0[e]; }
            else                 { src = s1[e]; dj = NN + d1[e]; }
            int p = atomicAdd(&cur[dj], 1);
            eidx[p] = src;
        }
        return;
    }
    if (blockIdx.x >= gemmBlocks) return;

    const float* X; const float* W; float* O; float* S;
    switch (blockIdx.y) {
        case 0: X = Xa; W = Wa; O = Oa; S = S0; break;
        case 1: X = Xb; W = Wb; O = Ob; S = S1; break;
        case 2: X = Xc; W = Wc; O = Oc; S = S2; break;
        default: X = Xd; W = Wd; O = Od; S = S3; break;
    }
    __shared__ __align__(16) float sW[K * 96];
    __shared__ __align__(8) ull sXp[K][33];
    __shared__ float wrS[K * 3];
    const int row0 = blockIdx.x * 64;

    for (int i = t; i < K * 96; i += 192) sW[i] = W[i];
    for (int i = t; i < K * 3; i += 192) wrS[i] = WR4[blockIdx.y * K * 3 + i];
    float* sXf = (float*)sXp;
    for (int i = t; i < 64 * K; i += 192) {
        int r = i / K, k = i - r * K;
        int gr = row0 + r;
        sXf[k * 66 + r] = (gr < N) ? X[(size_t)gr * K + k] : 0.f;
    }
    __syncthreads();

    const int cg = threadIdx.x;
    const int rg = threadIdx.y;
    ull acc[4][4];
    #pragma unroll
    for (int a = 0; a < 4; a++)
        #pragma unroll
        for (int b = 0; b < 4; b++) acc[a][b] = 0ull;

    #pragma unroll 8
    for (int k = 0; k < K; k++) {
        float4 w = *reinterpret_cast<const float4*>(&sW[k * 96 + cg * 4]);
        ull w0 = pack2(w.x, w.x), w1 = pack2(w.y, w.y);
        ull w2 = pack2(w.z, w.z), w3 = pack2(w.w, w.w);
        #pragma unroll
        for (int rp = 0; rp < 4; rp++) {
            ull xp = sXp[k][rg * 4 + rp];
            ffma2(acc[rp][0], xp, w0);
            ffma2(acc[rp][1], xp, w1);
            ffma2(acc[rp][2], xp, w2);
            ffma2(acc[rp][3], xp, w3);
        }
    }
    #pragma unroll
    for (int rp = 0; rp < 4; rp++) {
        int row = row0 + (rg * 4 + rp) * 2;
        float lo0, hi0, lo1, hi1, lo2, hi2, lo3, hi3;
        unpack2(lo0, hi0, acc[rp][0]); unpack2(lo1, hi1, acc[rp][1]);
        unpack2(lo2, hi2, acc[rp][2]); unpack2(lo3, hi3, acc[rp][3]);
        if (row < N)
            *reinterpret_cast<float4*>(&O[(size_t)row * 96 + cg * 4]) =
                make_float4(lo0, lo1, lo2, lo3);
        if (row + 1 < N)
            *reinterpret_cast<float4*>(&O[(size_t)(row + 1) * 96 + cg * 4]) =
                make_float4(hi0, hi1, hi2, hi3);
    }

    if (t < 64) {
        int gr = row0 + t;
        if (gr < N) {
            float v0 = 0.f, v1 = 0.f, v2 = 0.f;
            #pragma unroll 8
            for (int k = 0; k < K; k++) {
                float xv = sXf[k * 66 + t];
                v0 = fmaf(xv, wrS[k * 3 + 0], v0);
                v1 = fmaf(xv, wrS[k * 3 + 1], v1);
                v2 = fmaf(xv, wrS[k * 3 + 2], v2);
            }
            S[gr * 3 + 0] = v0;
            S[gr * 3 + 1] = v1;
            S[gr * 3 + 2] = v2;
        }
    }
}

// ---------------- launch 4/7: fused exp + gather, warp per (node, head) ----------------
__global__ void gat_expgather_kernel(const int* __restrict__ eidx, const int* __restrict__ off,
                                     const float* __restrict__ el, const float* __restrict__ er,
                                     const float* __restrict__ fs, const float* __restrict__ res,
                                     const float* __restrict__ bias0, const float* __restrict__ bias1,
                                     float* __restrict__ out0, float* __restrict__ out1,
                                     int totalE) {
    int gw = (blockIdx.x * blockDim.x + threadIdx.x) >> 5;
    int lane = threadIdx.x & 31;
    if (gw >= 2 * NN * 3) return;
    int w = gw / 3;
    int h = gw - 3 * w;
    const int rel  = (w >= NN);
    const int node = w - rel * NN;
    const float* ELr = el + (size_t)rel * NN * 3 + h;
    const float* FSr = fs + (size_t)rel * NN * 96 + h * 32 + lane;
    const float* RSr = res + (size_t)rel * NN * 96;
    const float* bias = rel ? bias1 : bias0;
    float* out = rel ? out1 : out0;

    int beg = off[w];
    int end = (w + 1 < 2 * NN) ? off[w + 1] : totalE;
    float erh = er[w * 3 + h];

    float a = 0.f, d = 0.f;
    for (int p = beg; p < end; p += 4) {
        #pragma unroll
        for (int j = 0; j < 4; j++) {
            int q = p + j;
            bool ok = q < end;
            int qs = ok ? q : beg;
            int s = eidx[qs];
            float v = ELr[s * 3] + erh;
            v = v > 0.f ? v : SLOPE * v;
            float e = ok ? __expf(v) : 0.f;
            a = fmaf(e, FSr[(size_t)s * 96], a);
            d += e;
        }
    }
    size_t o = (size_t)node * 96 + h * 32 + lane;
    out[o] = (d > 0.f ? a / d : 0.f) + RSr[o] + bias[h * 32 + lane];
}

// ---------------- launch 5/8: dual Linear+BN+ReLU (+ extra section) ----------------
// EXTRA: 0 = none, 1 = WR for next layer, 2 = cleanup (zero deg/state/ticket)
template <int EXTRA>
__global__ void lin_bn_relu_kernel(const float* __restrict__ in0, const float* __restrict__ in1,
                                   const float* __restrict__ Wb, const float* __restrict__ bb,
                                   const float* __restrict__ bnb,
                                   float* __restrict__ out0, float* __restrict__ out1,
                                   const float* __restrict__ nW0, const float* __restrict__ nW1,
                                   const float* __restrict__ nattn, float* __restrict__ WR,
                                   int nK, int* __restrict__ deg, int n) {
    const int t = threadIdx.x;  // 256
    if (blockIdx.y == 2) {
        int i = blockIdx.x * 256 + t;
        if (EXTRA == 1) {
            wr_section(nW0, nW1, nattn, WR, nK, i);
        } else if (EXTRA == 2) {
            if (i < 2 * NN) deg[i] = 0;
            if (i < 256) g_state[i] = 0u;
            if (i == 0) g_ticket = 0;
        }
        return;
    }
    const float* in  = blockIdx.y ? in1 : in0;
    const float* W   = Wb  + (blockIdx.y ? 96 * 32 : 0);
    const float* b   = bb  + (blockIdx.y ? 32 : 0);
    const float* bn  = bnb + (blockIdx.y ? 128 : 0);
    float*       out = blockIdx.y ? out1 : out0;

    __shared__ float sW[96 * 32];
    __shared__ float sIn[32][97];
    __shared__ float sScale[32], sShift[32];

    for (int i = t; i < 96 * 32; i += 256) sW[i] = W[i];
    if (t < 32) {
        float gamma = bn[t], beta = bn[32 + t], mean = bn[64 + t], var = bn[96 + t];
        float sc = gamma * rsqrtf(var + 1e-5f);
        sScale[t] = sc;
        sShift[t] = beta + (b[t] - mean) * sc;
    }
    const int node0 = blockIdx.x * 32;
    for (int i = t; i < 32 * 96; i += 256) {
        int r = i / 96, k = i - r * 96;
        int gn = node0 + r;
        sIn[r][k] = (gn < n) ? in[(size_t)gn * 96 + k] : 0.f;
    }
    __syncthreads();

    const int c = t & 31, ng = t >> 5;
    float acc[4] = {0.f, 0.f, 0.f, 0.f};
    #pragma unroll 8
    for (int k = 0; k < 96; k++) {
        float wv = sW[k * 32 + c];
        #pragma unroll
        for (int r = 0; r < 4; r++) acc[r] = fmaf(sIn[ng * 4 + r][k], wv, acc[r]);
    }
    #pragma unroll
    for (int r = 0; r < 4; r++) {
        int gn = node0 + ng * 4 + r;
        if (gn < n) {
            float y = acc[r] * sScale[c] + sShift[c];
            out[(size_t)gn * 32 + c] = y > 0.f ? y : 0.f;
        }
    }
}

// ==================================================================================
extern "C" void kernel_launch(void* const* d_in, const int* in_sizes, int n_in,
                              void* d_out, int out_size) {
    const float* emb_user = (const float*)d_in[0];
    const float* emb_item = (const float*)d_in[1];
    const float* W1    = (const float*)d_in[2];
    const float* attn1 = (const float*)d_in[3];
    const float* res1  = (const float*)d_in[4];
    const float* bias1 = (const float*)d_in[5];
    const float* nnW1  = (const float*)d_in[6];
    const float* nnb1  = (const float*)d_in[7];
    const float* bn1   = (const float*)d_in[8];
    const float* W2    = (const float*)d_in[9];
    const float* attn2 = (const float*)d_in[10];
    const float* res2  = (const float*)d_in[11];
    const float* bias2 = (const float*)d_in[12];
    const float* nnW2  = (const float*)d_in[13];
    const float* nnb2  = (const float*)d_in[14];
    const float* bn2   = (const float*)d_in[15];
    const int* go_src   = (const int*)d_in[16];
    const int* go_dst   = (const int*)d_in[17];
    const int* back_src = (const int*)d_in[18];
    const int* back_dst = (const int*)d_in[19];
    const int E = in_sizes[16];
    const int N = NN;

    float *FS, *RES, *EL, *ER, *GU, *GI, *HU, *HI, *WR;
    int *DEG, *OFF, *CUR, *EIDX;
    cudaGetSymbolAddress((void**)&FS,   g_FS);
    cudaGetSymbolAddress((void**)&RES,  g_RES);
    cudaGetSymbolAddress((void**)&EL,   g_EL);
    cudaGetSymbolAddress((void**)&ER,   g_ER);
    cudaGetSymbolAddress((void**)&GU,   g_GU);
    cudaGetSymbolAddress((void**)&GI,   g_GI);
    cudaGetSymbolAddress((void**)&HU,   g_HU);
    cudaGetSymbolAddress((void**)&HI,   g_HI);
    cudaGetSymbolAddress((void**)&WR,   g_WR);
    cudaGetSymbolAddress((void**)&DEG,  g_deg);
    cudaGetSymbolAddress((void**)&OFF,  g_off);
    cudaGetSymbolAddress((void**)&CUR,  g_cur);
    cudaGetSymbolAddress((void**)&EIDX, g_eidx);

    const int eb = (E + 255) / 256;                       // 1954
    const int scanBlocks = (2 * N + 1023) / 1024;         // 196
    const int gemmBlocks = (N + 63) / 64;                 // 1563
    const int scatBlocks = (E + 191) / 192;               // 2605
    const int megaX = scatBlocks > gemmBlocks ? scatBlocks : gemmBlocks;
    const int gatherBlocks = (2 * N * 3 * 32 + 255) / 256;
    const int lbBlocks = (N + 31) / 32;

    // 1: count degrees (both rels) + WR layer1   (DEG pre-zeroed by prior call / static init)
    pre_kernel<<<dim3(eb, 3), 256>>>(go_dst, back_dst, DEG,
                                     W1, W1 + 64 * 96, attn1, WR, 64, E);
    // 2: single-pass scan -> OFF, CUR
    scan_lb_kernel<<<scanBlocks, 1024>>>(DEG, OFF, CUR, 2 * N);
    // 3: layer-1 GEMM quad + attn scores + CSR scatter
    mega_kernel<64, true><<<dim3(megaX, 6), dim3(24, 8)>>>(
        emb_user, W1,             FS,
        emb_item, res1,           RES,
        emb_item, W1 + 64 * 96,   FS + (size_t)N * 96,
        emb_user, res1 + 64 * 96, RES + (size_t)N * 96,
        WR, EL, ER, EL + N * 3, ER + N * 3,
        go_src, go_dst, back_src, back_dst, CUR, EIDX,
        N, E, gemmBlocks);
    // 4 (PROFILED): layer-1 fused exp + gather
    gat_expgather_kernel<<<gatherBlocks, 256>>>(EIDX, OFF, EL, ER, FS, RES,
                                                bias1, bias1 + 96, GI, GU, 2 * E);
    // 5: layer-1 MLPs + WR layer2
    lin_bn_relu_kernel<1><<<dim3(lbBlocks, 3), 256>>>(GU, GI, nnW1, nnb1, bn1, HU, HI,
                                                      W2, W2 + 32 * 96, attn2, WR, 32,
                                                      DEG, N);
    // 6: layer-2 GEMM quad + attn scores
    mega_kernel<32, false><<<dim3(gemmBlocks, 4), dim3(24, 8)>>>(
        HU, W2,             FS,
        HI, res2,           RES,
        HI, W2 + 32 * 96,   FS + (size_t)N * 96,
        HU, res2 + 32 * 96, RES + (size_t)N * 96,
        WR, EL, ER, EL + N * 3, ER + N * 3,
        go_src, go_dst, back_src, back_dst, CUR, EIDX,
        N, E, gemmBlocks);
    // 7: layer-2 fused exp + gather
    gat_expgather_kernel<<<gatherBlocks, 256>>>(EIDX, OFF, EL, ER, FS, RES,
                                                bias2, bias2 + 96, GI, GU, 2 * E);
    // 8: output MLPs + cleanup (re-zero DEG/state/ticket for next call)
    float* out = (float*)d_out;
    lin_bn_relu_kernel<2><<<dim3(lbBlocks, 3), 256>>>(GU, GI, nnW2, nnb2, bn2,
                                                      out, out + (size_t)N * 32,
                                                      W2, W2, attn2, WR, 32,
                                                      DEG, N);
}